// round 15
// baseline (speedup 1.0000x reference)
#include <cuda_runtime.h>
#include <cuda_bf16.h>

#define FULL 0xffffffffu

namespace {
constexpr int NB   = 32;
constexpr int NP   = 32;
constexpr int DD   = 12;
constexpr int PP   = 32;
constexpr int LL   = 1024;
constexpr int LOUT = 32;
constexpr int CPL  = 8;            // cols per lane
constexpr int CP2  = CPL / 2;      // packed f32x2 pairs per lane
constexpr int WBLK = 32 * CPL;     // 256 cols per warp
constexpr int NBLK = LL / WBLK;    // 4 warps per (b,n)
constexpr int PTW  = 14;           // u64 words per pattern-row record (12 dims + p2 + pad)
constexpr float BIGV = 1e30f;
}

typedef unsigned long long u64;

// Blackwell packed fp32x2 ops (FFMA2/FADD2 in SASS — only reachable via PTX).
__device__ __forceinline__ u64 pack2(float lo, float hi) {
    u64 r; asm("mov.b64 %0, {%1, %2};" : "=l"(r) : "f"(lo), "f"(hi)); return r;
}
__device__ __forceinline__ void unpack2(u64 v, float& lo, float& hi) {
    asm("mov.b64 {%0, %1}, %2;" : "=f"(lo), "=f"(hi) : "l"(v));
}
__device__ __forceinline__ u64 ffma2(u64 a, u64 b, u64 c) {
    u64 d; asm("fma.rn.f32x2 %0, %1, %2, %3;" : "=l"(d) : "l"(a), "l"(b), "l"(c)); return d;
}
__device__ __forceinline__ u64 fadd2(u64 a, u64 b) {
    u64 d; asm("add.rn.f32x2 %0, %1, %2;" : "=l"(d) : "l"(a), "l"(b)); return d;
}
// Both-blocking named barrier over 64 threads (2 warps) — deadlock-free.
__device__ __forceinline__ void bar_pair(int id) {
    asm volatile("bar.sync %0, 64;" :: "r"(id) : "memory");
}

// One CTA (4 warps) per (b, n); warp w owns column block w (256 cols).
// Pairwise producer/consumer pipeline over 2-row steps with named barriers
// (R14, proven correct). This round attacks the MIO/shuffle throughput wall:
//  - pattern row fetched as 7 LDS.128 (one 112B record) instead of 13 LDS.64
//  - composite scan trimmed to 11 shfls/row: last hop shuffles B only, and
//    the left-boundary bl is folded into lane 0's local composite (constant
//    min-plus map), removing the exclusive-A shuffle entirely.
//
// Row recurrence (w == 1 exactly, RHO = 1.0):
//   cur[j] = c[j] + min(m[j], cur[j-1]),  m[j] = min(D[i-1,j-1], D[i-1,j])
// as composition of affine-min maps f(v) = min(beta, v + alpha).
__global__ void __launch_bounds__(128, 3)
dtw_fused_kernel(const float* __restrict__ x,
                 const float* __restrict__ patts,
                 float* __restrict__ out)
{
    const int gid  = blockIdx.x;        // 0..1023
    const int b    = gid >> 5;
    const int n    = gid & 31;
    const int w    = threadIdx.x >> 5;  // column block 0..3
    const int lane = threadIdx.x & 31;

    __shared__ alignas(16) u64 pt[PP][PTW];   // [d0..d11]=(-2p,-2p), [12]=(p2,p2), [13]=pad
    __shared__ float carry[NBLK - 1][PP];     // carry[w][i] = D[i][(w+1)*WBLK-1]

    // ---- pattern table: one thread per pattern row ----
    if (threadIdx.x < PP) {
        const int i = threadIdx.x;
        const float* pp = patts + n * (DD * PP) + i;
        float s2 = 0.0f;
        #pragma unroll
        for (int d = 0; d < DD; ++d) {
            float v = pp[d * PP];
            s2 = fmaf(v, v, s2);
            float m2 = -2.0f * v;
            pt[i][d] = pack2(m2, m2);
        }
        pt[i][12] = pack2(s2, s2);
        pt[i][13] = 0ull;
    }

    // ---- x chunk for this warp's column block (registers, packed f32x2) ----
    const float* xb = x + b * (DD * LL);
    const int j0 = w * WBLK;
    u64 xp[DD][CP2];
    u64 px2[CP2];
    {
        u64 z = pack2(0.0f, 0.0f);
        #pragma unroll
        for (int k2 = 0; k2 < CP2; ++k2) px2[k2] = z;
    }
    #pragma unroll
    for (int d = 0; d < DD; ++d) {
        const float* px = xb + d * LL + j0 + CPL * lane;
        float4 v0 = *reinterpret_cast<const float4*>(px);
        float4 v1 = *reinterpret_cast<const float4*>(px + 4);
        xp[d][0] = pack2(v0.x, v0.y);
        xp[d][1] = pack2(v0.z, v0.w);
        xp[d][2] = pack2(v1.x, v1.y);
        xp[d][3] = pack2(v1.z, v1.w);
        #pragma unroll
        for (int k2 = 0; k2 < CP2; ++k2)
            px2[k2] = ffma2(xp[d][k2], xp[d][k2], px2[k2]);
    }
    __syncthreads();   // pattern table visible to all warps

    float* outb = out + ((b * NP + n) * PP) * LOUT;
    float Dp[CPL];   // previous DP row for this warp's block

    // One full row update. On return Dp[k] == cur[k].
    auto rowcalc = [&](int i, float bl, float bm) {
        // ---- pattern record: 7 x LDS.128 (broadcast, conflict-free) ----
        const ulonglong2* pq = reinterpret_cast<const ulonglong2*>(pt[i]);
        ulonglong2 q0 = pq[0], q1 = pq[1], q2 = pq[2],
                   q3 = pq[3], q4 = pq[4], q5 = pq[5], q6 = pq[6];
        const u64 pd[12] = {q0.x, q0.y, q1.x, q1.y, q2.x, q2.y,
                            q3.x, q3.y, q4.x, q4.y, q5.x, q5.y};

        // ---- cost row (alpha) via packed FMAs ----
        u64 cc[CP2];
        #pragma unroll
        for (int k2 = 0; k2 < CP2; ++k2) cc[k2] = fadd2(q6.x, px2[k2]);
        #pragma unroll
        for (int d = 0; d < DD; ++d) {
            #pragma unroll
            for (int k2 = 0; k2 < CP2; ++k2)
                cc[k2] = ffma2(pd[d], xp[d][k2], cc[k2]);
        }
        float c[CPL];
        #pragma unroll
        for (int k2 = 0; k2 < CP2; ++k2)
            unpack2(cc[k2], c[2 * k2], c[2 * k2 + 1]);

        // ---- local inclusive composites (A = prefix sum of c, B = bound) ----
        float A[CPL], Bv[CPL];
        float shin = __shfl_up_sync(FULL, Dp[CPL - 1], 1);
        if (i == 0) {
            A[0] = c[0]; Bv[0] = BIGV;
            #pragma unroll
            for (int k = 1; k < CPL; ++k) { A[k] = A[k - 1] + c[k]; Bv[k] = BIGV; }
        } else {
            float m0 = fminf((lane == 0) ? bm : shin, Dp[0]);
            A[0]  = c[0];
            Bv[0] = c[0] + m0;
            #pragma unroll
            for (int k = 1; k < CPL; ++k) {
                float mk = fminf(Dp[k - 1], Dp[k]);
                A[k]  = A[k - 1] + c[k];
                Bv[k] = fminf(c[k] + mk, Bv[k - 1] + c[k]);
            }
        }

        // ---- fold left boundary into lane 0's composite (constant map) ----
        if (lane == 0) {
            #pragma unroll
            for (int k = 0; k < CPL; ++k) Bv[k] = fminf(Bv[k], bl + A[k]);
        }

        // ---- composite warp scan: 4 hops (A+B), last hop B-only ----
        float Aw = A[CPL - 1], Bw = Bv[CPL - 1];
        #pragma unroll
        for (int o = 1; o < 16; o <<= 1) {
            float Au = __shfl_up_sync(FULL, Aw, o);
            float Bu = __shfl_up_sync(FULL, Bw, o);
            if (lane >= o) {
                Bw = fminf(Bw, Bu + Aw);  // uses pre-update Aw
                Aw = Aw + Au;
            }
        }
        {
            float Bu = __shfl_up_sync(FULL, Bw, 16);
            if (lane >= 16) Bw = fminf(Bw, Bu + Aw);
        }
        float Bep  = __shfl_up_sync(FULL, Bw, 1);
        float base = (lane == 0) ? BIGV : Bep;   // lane0: Bv already holds bl-path

        // ---- cur[k] = min(Bv[k], base + A[k]) ----
        #pragma unroll
        for (int k = 0; k < CPL; ++k)
            Dp[k] = fminf(Bv[k], base + A[k]);

        // ---- output tail: cols 992..1023 = lanes 28..31 of last warp ----
        if (w == NBLK - 1 && lane >= 28) {
            float* po = outb + i * LOUT + (lane - 28) * CPL;
            *reinterpret_cast<float4*>(po)     = make_float4(Dp[0], Dp[1], Dp[2], Dp[3]);
            *reinterpret_cast<float4*>(po + 4) = make_float4(Dp[4], Dp[5], Dp[6], Dp[7]);
        }
    };

    float bmr = BIGV;   // carry[w-1][i0-1], held in a register across steps

    #pragma unroll 1
    for (int i0 = 0; i0 < PP; i0 += 2) {
        float bl0, bm0, bl1, bm1;
        if (w == 0) {
            bl0 = (i0 == 0) ? 0.0f : BIGV;   // D[0,0] seed enters via the fold
            bm0 = BIGV;                       // D[i-1][-1] always OOR at w==0
            bl1 = BIGV;
            bm1 = BIGV;
        } else {
            bar_pair(w);                      // rows 0..i0+1 of warp w-1 published
            bl0 = carry[w - 1][i0];
            bm0 = bmr;                        // = carry[w-1][i0-1]
            bl1 = carry[w - 1][i0 + 1];
            bm1 = bl0;                        // = carry[w-1][i0]
        }

        rowcalc(i0, bl0, bm0);
        if (w < NBLK - 1 && lane == 31) carry[w][i0] = Dp[CPL - 1];

        rowcalc(i0 + 1, bl1, bm1);
        if (w < NBLK - 1 && lane == 31) carry[w][i0 + 1] = Dp[CPL - 1];

        if (w < NBLK - 1) bar_pair(w + 1);    // hand both rows to warp w+1
        bmr = bl1;
    }
}

extern "C" void kernel_launch(void* const* d_in, const int* in_sizes, int n_in,
                              void* d_out, int out_size) {
    const float* x     = (const float*)d_in[0];   // [32, 12, 1024]
    const float* patts = (const float*)d_in[1];   // [32, 12, 32]
    float* out = (float*)d_out;                   // [32, 32, 32, 32]
    (void)in_sizes; (void)n_in; (void)out_size;
    dtw_fused_kernel<<<NB * NP, 128>>>(x, patts, out);
}